// round 1
// baseline (speedup 1.0000x reference)
#include <cuda_runtime.h>
#include <cstdint>

#define BB 2
#define CC 64
#define HH 384
#define WW 384
#define GG 4
#define OMD 112
#define OMU 108
#define HWSZ (HH*WW)
#define NPIX (BB*HH*WW)

// Scratch buffers (static device globals — allowed; no runtime allocation)
__device__ float g_value[(size_t)NPIX*CC];   // NHWC
__device__ float g_dw[(size_t)NPIX*CC];      // NHWC
__device__ float g_om[(size_t)NPIX*OMU];     // per-pixel 108 floats

// ---------------------------------------------------------------------------
// Kernel 1: value = x @ Wv + bv   (NHWC output)
// block = 128 pixels of one row, 256 threads. Wv column in registers.
// ---------------------------------------------------------------------------
__global__ void __launch_bounds__(256) k_value(const float* __restrict__ inp,
                                               const float* __restrict__ Wv,
                                               const float* __restrict__ bv) {
    __shared__ float xt[64][128];
    int blk  = blockIdx.x;
    int tile = blk % 3;
    int row  = (blk / 3) % HH;
    int b    = blk / (3 * HH);
    int x0   = tile * 128;
    int t    = threadIdx.x;

    const float* ibase = inp + (size_t)b * CC * HWSZ + (size_t)row * WW + x0;
    for (int i = t; i < 64 * 128; i += 256) {
        int ci = i >> 7, p = i & 127;
        xt[ci][p] = ibase[(size_t)ci * HWSZ + p];
    }

    int c = t & 63;
    float wreg[64];
#pragma unroll
    for (int k = 0; k < 64; k++) wreg[k] = Wv[k * 64 + c];
    float bvc = bv[c];
    __syncthreads();

    float* vbase = g_value + ((size_t)((b * HH + row) * WW) + x0) * 64 + c;
    int q0 = t >> 6;
    for (int qi = 0; qi < 8; qi++) {
        int p = (q0 + qi * 4) * 4;
        float4 acc = {bvc, bvc, bvc, bvc};
#pragma unroll
        for (int k = 0; k < 64; k++) {
            float4 xv = *reinterpret_cast<const float4*>(&xt[k][p]);
            float w = wreg[k];
            acc.x += w * xv.x; acc.y += w * xv.y;
            acc.z += w * xv.z; acc.w += w * xv.w;
        }
        vbase[(size_t)(p + 0) * 64] = acc.x;
        vbase[(size_t)(p + 1) * 64] = acc.y;
        vbase[(size_t)(p + 2) * 64] = acc.z;
        vbase[(size_t)(p + 3) * 64] = acc.w;
    }
}

// ---------------------------------------------------------------------------
// Kernel 2: depthwise 3x3 conv, zero padding, NHWC output
// block = 32 pixels of one row, 256 threads (8 warps x 4 px, 2 ch/lane)
// ---------------------------------------------------------------------------
__global__ void __launch_bounds__(256) k_dw(const float* __restrict__ inp,
                                            const float* __restrict__ Wdw,
                                            const float* __restrict__ bdw) {
    __shared__ float it[64][3][35];   // padded: per-channel stride 105 (odd) -> conflict-free
    int blk  = blockIdx.x;
    int tile = blk % 12;
    int row  = (blk / 12) % HH;
    int b    = blk / (12 * HH);
    int x0   = tile * 32;
    int t    = threadIdx.x;

    for (int i = t; i < 64 * 3 * 34; i += 256) {
        int ci  = i / 102;
        int rem = i - ci * 102;
        int r   = rem / 34;
        int xx  = rem - r * 34;
        int gy = row - 1 + r;
        int gx = x0 - 1 + xx;
        float v = 0.f;
        if (gy >= 0 && gy < HH && gx >= 0 && gx < WW)
            v = inp[(size_t)(b * CC + ci) * HWSZ + (size_t)gy * WW + gx];
        it[ci][r][xx] = v;
    }
    __syncthreads();

    int lane = t & 31, wrp = t >> 5;
    float wd0[9], wd1[9];
#pragma unroll
    for (int j = 0; j < 9; j++) {
        wd0[j] = Wdw[lane * 9 + j];
        wd1[j] = Wdw[(lane + 32) * 9 + j];
    }
    float b0 = bdw[lane], b1 = bdw[lane + 32];

    for (int i = 0; i < 4; i++) {
        int p = wrp * 4 + i;
        float a0 = b0, a1 = b1;
#pragma unroll
        for (int r = 0; r < 3; r++)
#pragma unroll
            for (int s = 0; s < 3; s++) {
                a0 += it[lane][r][p + s]      * wd0[r * 3 + s];
                a1 += it[lane + 32][r][p + s] * wd1[r * 3 + s];
            }
        float* o = g_dw + ((size_t)((b * HH + row) * WW) + x0 + p) * 64;
        o[lane]      = a0;
        o[lane + 32] = a1;
    }
}

// ---------------------------------------------------------------------------
// Kernel 3: om = dw @ Wom + bom (first 108 outputs only), packed per pixel
// block = 16 pixels, 256 threads; float4 over pixel quads
// ---------------------------------------------------------------------------
__global__ void __launch_bounds__(256) k_om(const float* __restrict__ Wom,
                                            const float* __restrict__ bom) {
    __shared__ float dwt[64][20];     // [channel][pixel], stride 20 -> float4 16B aligned
    __shared__ float wom_s[64][108];
    __shared__ float omt[16 * 108];
    __shared__ float bom_s[108];

    int blk  = blockIdx.x;
    int tile = blk % 24;
    int row  = (blk / 24) % HH;
    int b    = blk / (24 * HH);
    int x0   = tile * 16;
    size_t pixbase = (size_t)((b * HH + row) * WW) + x0;
    int t = threadIdx.x;

    const float* dwg = g_dw + pixbase * 64;
    for (int i = t; i < 16 * 64; i += 256) {
        int p = i >> 6, ci = i & 63;
        dwt[ci][p] = dwg[i];
    }
    for (int i = t; i < 64 * 108; i += 256) {
        int ci = i / 108, j = i - ci * 108;
        wom_s[ci][j] = Wom[ci * OMD + j];
    }
    if (t < 108) bom_s[t] = bom[t];
    __syncthreads();

    for (int idx = t; idx < 4 * 108; idx += 256) {
        int q = idx & 3, j = idx >> 2;
        float bb = bom_s[j];
        float4 acc = {bb, bb, bb, bb};
#pragma unroll
        for (int ci = 0; ci < 64; ci++) {
            float w = wom_s[ci][j];
            float4 d = *reinterpret_cast<const float4*>(&dwt[ci][4 * q]);
            acc.x += w * d.x; acc.y += w * d.y;
            acc.z += w * d.z; acc.w += w * d.w;
        }
        omt[(4 * q + 0) * 108 + j] = acc.x;
        omt[(4 * q + 1) * 108 + j] = acc.y;
        omt[(4 * q + 2) * 108 + j] = acc.z;
        omt[(4 * q + 3) * 108 + j] = acc.w;
    }
    __syncthreads();

    float* og = g_om + pixbase * OMU;
    for (int i = t; i < 16 * 108; i += 256) og[i] = omt[i];
}

// ---------------------------------------------------------------------------
// Kernel 4: deformable sampling + output GEMM (@Wo), NCHW output
// block = 32 pixels of one row, 256 threads.
// Sampling: warp per pixel; lane = (group g = lane>>3, channel pair)
// ---------------------------------------------------------------------------
__global__ void __launch_bounds__(256) k_sample(const float* __restrict__ Wo,
                                                float* __restrict__ out) {
    __shared__ float wo_s[64][64];
    __shared__ float om_s[32][108];
    __shared__ float sb[32][66];     // sb[pixel][channel], pad 66 for float2 banks
    __shared__ float ost[64][33];    // staged output [co][pixel]

    int blk  = blockIdx.x;
    int tile = blk % 12;
    int row  = (blk / 12) % HH;
    int b    = blk / (12 * HH);
    int x0   = tile * 32;
    size_t pixbase = (size_t)((b * HH + row) * WW) + x0;
    int t = threadIdx.x;

    for (int i = t; i < 64 * 64; i += 256) wo_s[i >> 6][i & 63] = Wo[i];
    const float* omg = g_om + pixbase * OMU;
    for (int i = t; i < 32 * 108; i += 256) om_s[i / 108][i % 108] = omg[i];
    __syncthreads();

    int lane = t & 31, wrp = t >> 5;
    int g  = lane >> 3;              // group 0..3
    int cm = (lane & 7) * 2;         // channel pair within group
    int cbase = g * 16 + cm;
    float yf = (float)row;

    for (int i = 0; i < 4; i++) {
        int p = wrp * 4 + i;
        float xf = (float)(x0 + p);
        const float* omp = &om_s[p][g * 27];
        float2 acc = {0.f, 0.f};
#pragma unroll
        for (int k = 0; k < 9; k++) {
            int kx = k % 3 - 1;
            int ky = k / 3 - 1;
            float dx = omp[2 * k];
            float dy = omp[2 * k + 1];
            float m  = omp[18 + k];
            float px = xf + (float)kx + dx;
            float py = yf + (float)ky + dy;
            float x0f = floorf(px), y0f = floorf(py);
            float wx1 = px - x0f, wy1 = py - y0f;
            int xi = (int)x0f, yi = (int)y0f;
#pragma unroll
            for (int dyy = 0; dyy < 2; dyy++) {
                int yy = yi + dyy;
                float wy = dyy ? wy1 : 1.f - wy1;
                bool vy = (yy >= 0) && (yy < HH);
                int yc = min(max(yy, 0), HH - 1);
#pragma unroll
                for (int dxx = 0; dxx < 2; dxx++) {
                    int xx = xi + dxx;
                    float wx = dxx ? wx1 : 1.f - wx1;
                    bool vx = (xx >= 0) && (xx < WW);
                    int xc = min(max(xx, 0), WW - 1);
                    float wgt = (vx && vy) ? (wy * wx * m) : 0.f;
                    const float2 v = *reinterpret_cast<const float2*>(
                        g_value + ((size_t)((b * HH + yc) * WW) + xc) * 64 + cbase);
                    acc.x += wgt * v.x;
                    acc.y += wgt * v.y;
                }
            }
        }
        *reinterpret_cast<float2*>(&sb[p][cbase]) = acc;
    }
    __syncthreads();

    // output GEMM: out[co] = sum_c s[c] * Wo[c][co]; items = 16 co-quads x 32 px
    for (int idx = t; idx < 512; idx += 256) {
        int coq = idx & 15, p = idx >> 4;
        int co = coq * 4;
        float4 acc = {0.f, 0.f, 0.f, 0.f};
#pragma unroll
        for (int ci = 0; ci < 64; ci++) {
            float s = sb[p][ci];
            float4 w = *reinterpret_cast<const float4*>(&wo_s[ci][co]);
            acc.x += s * w.x; acc.y += s * w.y;
            acc.z += s * w.z; acc.w += s * w.w;
        }
        ost[co + 0][p] = acc.x;
        ost[co + 1][p] = acc.y;
        ost[co + 2][p] = acc.z;
        ost[co + 3][p] = acc.w;
    }
    __syncthreads();

    float* ob = out + (size_t)b * CC * HWSZ + (size_t)row * WW + x0;
    for (int i = t; i < 2048; i += 256) {
        int co = i >> 5, p = i & 31;
        ob[(size_t)co * HWSZ + p] = ost[co][p];
    }
}

// ---------------------------------------------------------------------------
extern "C" void kernel_launch(void* const* d_in, const int* in_sizes, int n_in,
                              void* d_out, int out_size) {
    const float* inp = (const float*)d_in[0];
    const float* Wv  = (const float*)d_in[1];
    const float* bv  = (const float*)d_in[2];
    const float* Wdw = (const float*)d_in[3];
    const float* bdw = (const float*)d_in[4];
    const float* Wom = (const float*)d_in[5];
    const float* bom = (const float*)d_in[6];
    const float* Wo  = (const float*)d_in[7];
    float* out = (float*)d_out;

    k_value <<<BB * HH * 3,  256>>> (inp, Wv, bv);
    k_dw    <<<BB * HH * 12, 256>>> (inp, Wdw, bdw);
    k_om    <<<BB * HH * 24, 256>>> (Wom, bom);
    k_sample<<<BB * HH * 12, 256>>> (Wo, out);
}

// round 2
// speedup vs baseline: 3.1647x; 3.1647x over previous
#include <cuda_runtime.h>
#include <cstdint>

#define BB 2
#define CC 64
#define HH 384
#define WW 384
#define OMD 112
#define OMU 108
#define HWSZ (HH*WW)
#define NPIX (BB*HH*WW)

// Scratch (static device globals, 16B aligned for vector access)
__device__ __align__(16) float g_value[(size_t)NPIX*CC];   // NHWC
__device__ __align__(16) float g_om[(size_t)NPIX*OMU];     // 108 f/px
__device__ __align__(16) float g_samp[(size_t)NPIX*CC];    // NHWC sampled

// ---------------------------------------------------------------------------
// Kernel 1: value = x @ Wv + bv   (NCHW in -> NHWC out)
// 64 px x 64 cout tile, 256 threads, 4x4 register tiles.
// ---------------------------------------------------------------------------
__global__ void __launch_bounds__(256) k_value(const float* __restrict__ inp,
                                               const float* __restrict__ Wv,
                                               const float* __restrict__ bv) {
    __shared__ float As[64][68];   // [cin][px]
    __shared__ float Bs[64][68];   // [cin][cout]
    int t   = threadIdx.x;
    int px0 = blockIdx.x * 64;
    int b   = px0 / HWSZ;
    int hw0 = px0 % HWSZ;

    const float* ib = inp + (size_t)b * CC * HWSZ + hw0;
    for (int idx = t; idx < 1024; idx += 256) {
        int c = idx >> 4, q = idx & 15;
        *reinterpret_cast<float4*>(&As[c][q * 4]) =
            *reinterpret_cast<const float4*>(ib + (size_t)c * HWSZ + q * 4);
    }
    for (int idx = t; idx < 1024; idx += 256) {
        int c = idx >> 4, q = idx & 15;
        *reinterpret_cast<float4*>(&Bs[c][q * 4]) =
            *reinterpret_cast<const float4*>(Wv + c * 64 + q * 4);
    }
    __syncthreads();

    int tx = t & 15, ty = t >> 4;           // cout quad, px quad
    float4 bvv = *reinterpret_cast<const float4*>(bv + tx * 4);
    float acc[4][4];
#pragma unroll
    for (int i = 0; i < 4; i++) {
        acc[i][0] = bvv.x; acc[i][1] = bvv.y; acc[i][2] = bvv.z; acc[i][3] = bvv.w;
    }
#pragma unroll
    for (int k = 0; k < 64; k++) {
        float4 a = *reinterpret_cast<float4*>(&As[k][ty * 4]);
        float4 w = *reinterpret_cast<float4*>(&Bs[k][tx * 4]);
        float av[4] = {a.x, a.y, a.z, a.w};
        float wv[4] = {w.x, w.y, w.z, w.w};
#pragma unroll
        for (int i = 0; i < 4; i++)
#pragma unroll
            for (int j = 0; j < 4; j++) acc[i][j] += av[i] * wv[j];
    }

    float* vb = g_value + (size_t)px0 * 64;
#pragma unroll
    for (int i = 0; i < 4; i++) {
        float4 o = {acc[i][0], acc[i][1], acc[i][2], acc[i][3]};
        *reinterpret_cast<float4*>(vb + (ty * 4 + i) * 64 + tx * 4) = o;
    }
}

// ---------------------------------------------------------------------------
// Kernel 2 (fused): depthwise 3x3 conv + om GEMM (64 -> 108) + bias
// 32 px of one row per block. dw stays in smem. Dynamic smem (~64KB).
// ---------------------------------------------------------------------------
extern __shared__ float dyn_smem[];
__global__ void __launch_bounds__(256) k_dwom(const float* __restrict__ inp,
                                              const float* __restrict__ Wdw,
                                              const float* __restrict__ bdw,
                                              const float* __restrict__ Wom,
                                              const float* __restrict__ bom) {
    // layout: it[64][3][35] | wom_s[64][112] | dwt[64][36] | bom_s[112]
    float* it    = dyn_smem;                    // 6720 floats
    float* wom_s = it + 64 * 3 * 35;            // 7168 floats
    float* dwt   = wom_s + 64 * 112;            // 2304 floats
    float* bom_s = dwt + 64 * 36;               // 112 floats

    int blk  = blockIdx.x;
    int tile = blk % 12;
    int row  = (blk / 12) % HH;
    int b    = blk / (12 * HH);
    int x0   = tile * 32;
    int t    = threadIdx.x;

    for (int i = t; i < 64 * 3 * 34; i += 256) {
        int ci  = i / 102;
        int rem = i - ci * 102;
        int r   = rem / 34;
        int xx  = rem - r * 34;
        int gy = row - 1 + r;
        int gx = x0 - 1 + xx;
        float v = 0.f;
        if (gy >= 0 && gy < HH && gx >= 0 && gx < WW)
            v = inp[(size_t)(b * CC + ci) * HWSZ + (size_t)gy * WW + gx];
        it[ci * 105 + r * 35 + xx] = v;
    }
    for (int idx = t; idx < 1792; idx += 256) {   // 64*112/4
        int c = idx / 28, q = idx % 28;
        *reinterpret_cast<float4*>(&wom_s[c * 112 + q * 4]) =
            *reinterpret_cast<const float4*>(Wom + c * OMD + q * 4);
    }
    if (t < 112) bom_s[t] = bom[t];
    __syncthreads();

    // depthwise: each thread fixed channel c = t&63, 8 pixels
    {
        int c = t & 63;
        float wd[9];
#pragma unroll
        for (int j = 0; j < 9; j++) wd[j] = Wdw[c * 9 + j];
        float bd = bdw[c];
        const float* itc = it + c * 105;
#pragma unroll
        for (int i = 0; i < 8; i++) {
            int p = (t >> 6) + i * 4;        // 0..31
            float a = bd;
#pragma unroll
            for (int r = 0; r < 3; r++)
#pragma unroll
                for (int s = 0; s < 3; s++)
                    a += itc[r * 35 + p + s] * wd[r * 3 + s];
            dwt[c * 36 + p] = a;
        }
    }
    __syncthreads();

    // GEMM: 32px x 108j, thread tiles 4px x 4j -> 8*27 = 216 active threads
    if (t < 216) {
        int tj = t % 27, tp = t / 27;
        float acc[4][4];
#pragma unroll
        for (int i = 0; i < 4; i++)
#pragma unroll
            for (int j = 0; j < 4; j++) acc[i][j] = bom_s[tj * 4 + j];
#pragma unroll
        for (int k = 0; k < 64; k++) {
            float4 a = *reinterpret_cast<float4*>(&dwt[k * 36 + tp * 4]);
            float4 w = *reinterpret_cast<float4*>(&wom_s[k * 112 + tj * 4]);
            float av[4] = {a.x, a.y, a.z, a.w};
            float wv[4] = {w.x, w.y, w.z, w.w};
#pragma unroll
            for (int i = 0; i < 4; i++)
#pragma unroll
                for (int j = 0; j < 4; j++) acc[i][j] += av[i] * wv[j];
        }
        size_t pixbase = (size_t)(b * HH + row) * WW + x0;
        float* og = g_om + pixbase * OMU;
#pragma unroll
        for (int i = 0; i < 4; i++) {
            float4 o = {acc[i][0], acc[i][1], acc[i][2], acc[i][3]};
            *reinterpret_cast<float4*>(og + (tp * 4 + i) * OMU + tj * 4) = o;
        }
    }
}

// ---------------------------------------------------------------------------
// Kernel 3: deformable bilinear sampling only -> g_samp (NHWC)
// 32 px per block, warp per 4 px; lane = (group, channel pair)
// ---------------------------------------------------------------------------
__global__ void __launch_bounds__(256, 3) k_sample() {
    __shared__ float om_s[32 * 108];
    int blk  = blockIdx.x;
    int tile = blk % 12;
    int row  = (blk / 12) % HH;
    int b    = blk / (12 * HH);
    int x0   = tile * 32;
    size_t pixbase = (size_t)(b * HH + row) * WW + x0;
    int t = threadIdx.x;

    const float4* omg = reinterpret_cast<const float4*>(g_om + pixbase * OMU);
    float4* oms4 = reinterpret_cast<float4*>(om_s);
    for (int i = t; i < 32 * 27; i += 256) oms4[i] = omg[i];
    __syncthreads();

    int lane = t & 31, wrp = t >> 5;
    int g  = lane >> 3;
    int cbase = g * 16 + (lane & 7) * 2;
    const float* vb = g_value + (size_t)b * HWSZ * 64;
    float* sbuf = g_samp + pixbase * 64;
    float yf = (float)row;

    for (int i = 0; i < 4; i++) {
        int p = wrp * 4 + i;
        float xf = (float)(x0 + p);
        const float* omp = &om_s[p * 108 + g * 27];
        float accx = 0.f, accy = 0.f;
#pragma unroll 3
        for (int k = 0; k < 9; k++) {
            float dx = omp[2 * k];
            float dy = omp[2 * k + 1];
            float m  = omp[18 + k];
            float px = xf + (float)(k % 3 - 1) + dx;
            float py = yf + (float)(k / 3 - 1) + dy;
            float x0f = floorf(px), y0f = floorf(py);
            float wx1 = px - x0f, wy1 = py - y0f;
            int xi = (int)x0f, yi = (int)y0f;
            float wx0 = 1.f - wx1, wy0 = (1.f - wy1) * m;
            wy1 *= m;
#pragma unroll
            for (int dyy = 0; dyy < 2; dyy++) {
                int yy = yi + dyy;
                float wy = dyy ? wy1 : wy0;
                bool vyd = (yy >= 0) && (yy < HH);
                int yc = min(max(yy, 0), HH - 1);
#pragma unroll
                for (int dxx = 0; dxx < 2; dxx++) {
                    int xx = xi + dxx;
                    float wx = dxx ? wx1 : wx0;
                    bool vxd = (xx >= 0) && (xx < WW);
                    int xc = min(max(xx, 0), WW - 1);
                    float wgt = (vxd && vyd) ? (wy * wx) : 0.f;
                    int o = (yc * WW + xc) * 64 + cbase;
                    float2 v = *reinterpret_cast<const float2*>(vb + o);
                    accx += wgt * v.x;
                    accy += wgt * v.y;
                }
            }
        }
        float2 r = {accx, accy};
        *reinterpret_cast<float2*>(sbuf + p * 64 + cbase) = r;
    }
}

// ---------------------------------------------------------------------------
// Kernel 4: out = samp @ Wo   (NHWC in -> NCHW out)
// ---------------------------------------------------------------------------
__global__ void __launch_bounds__(256) k_out(const float* __restrict__ Wo,
                                             float* __restrict__ out) {
    __shared__ float As[64][68];   // [cin][px]
    __shared__ float Bs[64][68];   // [cin][cout]
    int t   = threadIdx.x;
    int px0 = blockIdx.x * 64;
    int b   = px0 / HWSZ;
    int hw0 = px0 % HWSZ;

    const float* sp = g_samp + (size_t)px0 * 64;
    for (int idx = t; idx < 1024; idx += 256) {
        int px = idx >> 4, cq = idx & 15;
        float4 v = *reinterpret_cast<const float4*>(sp + px * 64 + cq * 4);
        As[cq * 4 + 0][px] = v.x;
        As[cq * 4 + 1][px] = v.y;
        As[cq * 4 + 2][px] = v.z;
        As[cq * 4 + 3][px] = v.w;
    }
    for (int idx = t; idx < 1024; idx += 256) {
        int c = idx >> 4, q = idx & 15;
        *reinterpret_cast<float4*>(&Bs[c][q * 4]) =
            *reinterpret_cast<const float4*>(Wo + c * 64 + q * 4);
    }
    __syncthreads();

    int tx = t & 15, ty = t >> 4;
    float acc[4][4];
#pragma unroll
    for (int i = 0; i < 4; i++)
#pragma unroll
        for (int j = 0; j < 4; j++) acc[i][j] = 0.f;
#pragma unroll
    for (int k = 0; k < 64; k++) {
        float4 a = *reinterpret_cast<float4*>(&As[k][ty * 4]);
        float4 w = *reinterpret_cast<float4*>(&Bs[k][tx * 4]);
        float av[4] = {a.x, a.y, a.z, a.w};
        float wv[4] = {w.x, w.y, w.z, w.w};
#pragma unroll
        for (int i = 0; i < 4; i++)
#pragma unroll
            for (int j = 0; j < 4; j++) acc[i][j] += av[i] * wv[j];
    }

    float* ob = out + (size_t)b * CC * HWSZ + hw0;
#pragma unroll
    for (int j = 0; j < 4; j++) {
        int co = tx * 4 + j;
        float4 o = {acc[0][j], acc[1][j], acc[2][j], acc[3][j]};
        *reinterpret_cast<float4*>(ob + (size_t)co * HWSZ + ty * 4) = o;
    }
}

// ---------------------------------------------------------------------------
extern "C" void kernel_launch(void* const* d_in, const int* in_sizes, int n_in,
                              void* d_out, int out_size) {
    const float* inp = (const float*)d_in[0];
    const float* Wv  = (const float*)d_in[1];
    const float* bv  = (const float*)d_in[2];
    const float* Wdw = (const float*)d_in[3];
    const float* bdw = (const float*)d_in[4];
    const float* Wom = (const float*)d_in[5];
    const float* bom = (const float*)d_in[6];
    const float* Wo  = (const float*)d_in[7];
    float* out = (float*)d_out;

    static int smem_set = 0;
    const int DWOM_SMEM = (64 * 3 * 35 + 64 * 112 + 64 * 36 + 112) * 4;
    if (!smem_set) {
        cudaFuncSetAttribute(k_dwom, cudaFuncAttributeMaxDynamicSharedMemorySize,
                             DWOM_SMEM);
        smem_set = 1;
    }

    k_value <<<NPIX / 64,   256>>> (inp, Wv, bv);
    k_dwom  <<<BB * HH * 12, 256, DWOM_SMEM>>> (inp, Wdw, bdw, Wom, bom);
    k_sample<<<BB * HH * 12, 256>>> ();
    k_out   <<<NPIX / 64,   256>>> (Wo, out);
}